// round 1
// baseline (speedup 1.0000x reference)
#include <cuda_runtime.h>

#define L_DIM 1024
#define N_DIM 4096
#define IMG_DIM 1024
#define NHEADS 4
#define NCHUNK 8   // split-K chunks for score reduction

// -------- scratch (no allocs allowed) --------
__device__ float g_q[L_DIM * N_DIM];                 // L_query [1024,4096]
__device__ float g_keys[NHEADS * L_DIM * N_DIM];     // keys [4,1024,4096]
__device__ float g_partial[NCHUNK * NHEADS * N_DIM]; // score partial sums
__device__ float g_weight[NHEADS * N_DIM];           // softmax weights
__device__ float g_fused[L_DIM * N_DIM];             // LN output

// ---------------- SGEMM: C[M,N] = A[M,K] * B[K,N] + bias[M] ----------------
// BM=BN=128, BK=16, TM=TN=8, 256 threads.
__global__ __launch_bounds__(256) void sgemm_bias(
    const float* __restrict__ A, const float* __restrict__ B,
    const float* __restrict__ bias, float* __restrict__ C,
    int M, int N, int K)
{
    constexpr int BM = 128, BN = 128, BK = 16, TM = 8, TN = 8;
    __shared__ alignas(16) float As[BK][BM];
    __shared__ alignas(16) float Bs[BK][BN];

    const int tid = threadIdx.x;
    const int bm  = blockIdx.y * BM;
    const int bn  = blockIdx.x * BN;
    const int tx  = tid & 15;   // 16 cols of threads
    const int ty  = tid >> 4;   // 16 rows of threads

    float acc[TM][TN];
    #pragma unroll
    for (int i = 0; i < TM; i++)
        #pragma unroll
        for (int j = 0; j < TN; j++)
            acc[i][j] = 0.0f;

    for (int k0 = 0; k0 < K; k0 += BK) {
        // load A tile (BM x BK) transposed into As[k][m]; B tile (BK x BN) straight
        #pragma unroll
        for (int l = 0; l < 2; l++) {
            int f  = tid + l * 256;          // 0..511 float4 slots
            int ar = f >> 2, ac = (f & 3) << 2;
            float4 va = *reinterpret_cast<const float4*>(
                &A[(size_t)(bm + ar) * K + k0 + ac]);
            As[ac + 0][ar] = va.x;
            As[ac + 1][ar] = va.y;
            As[ac + 2][ar] = va.z;
            As[ac + 3][ar] = va.w;

            int br = f >> 5, bc = (f & 31) << 2;
            *reinterpret_cast<float4*>(&Bs[br][bc]) =
                *reinterpret_cast<const float4*>(
                    &B[(size_t)(k0 + br) * N + bn + bc]);
        }
        __syncthreads();

        #pragma unroll
        for (int k = 0; k < BK; k++) {
            float ra[TM], rb[TN];
            *reinterpret_cast<float4*>(ra)     = *reinterpret_cast<float4*>(&As[k][ty * TM]);
            *reinterpret_cast<float4*>(ra + 4) = *reinterpret_cast<float4*>(&As[k][ty * TM + 4]);
            *reinterpret_cast<float4*>(rb)     = *reinterpret_cast<float4*>(&Bs[k][tx * TN]);
            *reinterpret_cast<float4*>(rb + 4) = *reinterpret_cast<float4*>(&Bs[k][tx * TN + 4]);
            #pragma unroll
            for (int i = 0; i < TM; i++)
                #pragma unroll
                for (int j = 0; j < TN; j++)
                    acc[i][j] += ra[i] * rb[j];
        }
        __syncthreads();
    }

    #pragma unroll
    for (int i = 0; i < TM; i++) {
        float bv = bias[bm + ty * TM + i];
        float4 o0 = make_float4(acc[i][0] + bv, acc[i][1] + bv,
                                acc[i][2] + bv, acc[i][3] + bv);
        float4 o1 = make_float4(acc[i][4] + bv, acc[i][5] + bv,
                                acc[i][6] + bv, acc[i][7] + bv);
        float* cp = &C[(size_t)(bm + ty * TM + i) * N + bn + tx * TN];
        *reinterpret_cast<float4*>(cp)     = o0;
        *reinterpret_cast<float4*>(cp + 4) = o1;
    }
}

// ------------- score partials: partial[chunk][h][n] = sum_{c in chunk} keys*q -------------
__global__ __launch_bounds__(256) void score_partial(
    const float* __restrict__ keys, const float* __restrict__ q,
    float* __restrict__ partial)
{
    int n     = blockIdx.x * 256 + threadIdx.x;   // gridDim.x = 16
    int chunk = blockIdx.y;                        // gridDim.y = NCHUNK
    int c0    = chunk * (L_DIM / NCHUNK);

    float s[NHEADS] = {0.f, 0.f, 0.f, 0.f};
    for (int c = c0; c < c0 + L_DIM / NCHUNK; c++) {
        float qv = q[(size_t)c * N_DIM + n];
        #pragma unroll
        for (int h = 0; h < NHEADS; h++)
            s[h] += keys[((size_t)(h * L_DIM + c)) * N_DIM + n] * qv;
    }
    #pragma unroll
    for (int h = 0; h < NHEADS; h++)
        partial[((size_t)chunk * NHEADS + h) * N_DIM + n] = s[h];
}

// ------------- softmax over heads; write weights + weightmap output -------------
__global__ __launch_bounds__(256) void softmax_heads(
    const float* __restrict__ partial, float* __restrict__ weight,
    float* __restrict__ wmap_out)
{
    int n = blockIdx.x * 256 + threadIdx.x;       // gridDim.x = 16
    float s[NHEADS] = {0.f, 0.f, 0.f, 0.f};
    for (int ch = 0; ch < NCHUNK; ch++)
        #pragma unroll
        for (int h = 0; h < NHEADS; h++)
            s[h] += partial[((size_t)ch * NHEADS + h) * N_DIM + n];

    const float inv_sqrt_dk = 1.0f / 32.0f;       // sqrt(1024) = 32
    float m = -1e30f;
    #pragma unroll
    for (int h = 0; h < NHEADS; h++) { s[h] *= inv_sqrt_dk; m = fmaxf(m, s[h]); }
    float e[NHEADS], sum = 0.f;
    #pragma unroll
    for (int h = 0; h < NHEADS; h++) { e[h] = __expf(s[h] - m); sum += e[h]; }
    float inv = 1.0f / sum;
    #pragma unroll
    for (int h = 0; h < NHEADS; h++) {
        float w = e[h] * inv;
        weight[(size_t)h * N_DIM + n]   = w;
        wmap_out[(size_t)h * N_DIM + n] = w;
    }
}

// ------------- z = sum_h w*keys; fused = LayerNorm(z + q) over N -------------
__global__ __launch_bounds__(256) void z_layernorm(
    const float* __restrict__ keys, const float* __restrict__ q,
    const float* __restrict__ weight, const float* __restrict__ gamma,
    const float* __restrict__ beta, float* __restrict__ fused)
{
    int c = blockIdx.x;                            // 1024 blocks, one row each
    __shared__ float t[N_DIM];
    __shared__ float r1[8], r2[8];
    __shared__ float s_mean, s_rstd;

    float lsum = 0.f, lsq = 0.f;
    for (int n = threadIdx.x; n < N_DIM; n += 256) {
        float v = q[(size_t)c * N_DIM + n];
        #pragma unroll
        for (int h = 0; h < NHEADS; h++)
            v += weight[(size_t)h * N_DIM + n] *
                 keys[((size_t)(h * L_DIM + c)) * N_DIM + n];
        t[n] = v;
        lsum += v;
        lsq  += v * v;
    }
    #pragma unroll
    for (int o = 16; o > 0; o >>= 1) {
        lsum += __shfl_xor_sync(0xffffffffu, lsum, o);
        lsq  += __shfl_xor_sync(0xffffffffu, lsq, o);
    }
    int wid = threadIdx.x >> 5, lid = threadIdx.x & 31;
    if (lid == 0) { r1[wid] = lsum; r2[wid] = lsq; }
    __syncthreads();
    if (threadIdx.x == 0) {
        float ts = 0.f, tq = 0.f;
        #pragma unroll
        for (int i = 0; i < 8; i++) { ts += r1[i]; tq += r2[i]; }
        float mean = ts * (1.0f / N_DIM);
        float var  = tq * (1.0f / N_DIM) - mean * mean;
        s_mean = mean;
        s_rstd = rsqrtf(var + 1e-5f);
    }
    __syncthreads();
    float mean = s_mean, rstd = s_rstd;
    for (int n = threadIdx.x; n < N_DIM; n += 256)
        fused[(size_t)c * N_DIM + n] = (t[n] - mean) * rstd * gamma[n] + beta[n];
}

// ---------------- launch ----------------
extern "C" void kernel_launch(void* const* d_in, const int* in_sizes, int n_in,
                              void* d_out, int out_size)
{
    const float* point = (const float*)d_in[0];  // [1,1024,4096]
    const float* img   = (const float*)d_in[1];  // [1,1024,4096]
    const float* W_img = (const float*)d_in[2];  // [4,1024,1024]
    const float* b_img = (const float*)d_in[3];  // [4,1024]
    const float* W_L   = (const float*)d_in[4];  // [1024,1024]
    const float* b_L   = (const float*)d_in[5];  // [1024]
    const float* ln_g  = (const float*)d_in[6];  // [4096]
    const float* ln_b  = (const float*)d_in[7];  // [4096]
    const float* W_f   = (const float*)d_in[8];  // [1024,1024]
    const float* b_f   = (const float*)d_in[9];  // [1024]

    float* out  = (float*)d_out;                       // fusion_features [1024,4096]
    float* wmap = out + (size_t)L_DIM * N_DIM;         // weightmap [4,4096]

    float *q, *keys, *partial, *weight, *fused;
    cudaGetSymbolAddress((void**)&q,       g_q);
    cudaGetSymbolAddress((void**)&keys,    g_keys);
    cudaGetSymbolAddress((void**)&partial, g_partial);
    cudaGetSymbolAddress((void**)&weight,  g_weight);
    cudaGetSymbolAddress((void**)&fused,   g_fused);

    // 1) L_query = W_L * point + b_L          [1024,4096]
    sgemm_bias<<<dim3(N_DIM / 128, L_DIM / 128), 256>>>(
        W_L, point, b_L, q, L_DIM, N_DIM, IMG_DIM);

    // 2) keys = W_img * img + b_img (all heads as one M=4096 GEMM)
    sgemm_bias<<<dim3(N_DIM / 128, (NHEADS * L_DIM) / 128), 256>>>(
        W_img, img, b_img, keys, NHEADS * L_DIM, N_DIM, IMG_DIM);

    // 3) score partial sums over row chunks
    score_partial<<<dim3(N_DIM / 256, NCHUNK), 256>>>(keys, q, partial);

    // 4) reduce + softmax over heads; emit weightmap
    softmax_heads<<<N_DIM / 256, 256>>>(partial, weight, wmap);

    // 5) z + residual + LayerNorm
    z_layernorm<<<L_DIM, 256>>>(keys, q, weight, ln_g, ln_b, fused);

    // 6) fusion_features = W_f * fused + b_f
    sgemm_bias<<<dim3(N_DIM / 128, L_DIM / 128), 256>>>(
        W_f, fused, b_f, out, L_DIM, N_DIM, IMG_DIM);
}

// round 3
// speedup vs baseline: 2.5276x; 2.5276x over previous
#include <cuda_runtime.h>
#include <cuda_bf16.h>
#include <cstdint>

#define L_DIM 1024
#define N_DIM 4096
#define K_DIM 1024
#define NHEADS 4
#define NCHUNK 8

// ---------------- scratch (device globals; no allocs allowed) ----------------
__device__ float g_q[L_DIM * N_DIM];
__device__ float g_keys[NHEADS * L_DIM * N_DIM];
__device__ float g_partial[NCHUNK * NHEADS * N_DIM];
__device__ float g_weight[NHEADS * N_DIM];
__device__ float g_fused[L_DIM * N_DIM];

__device__ __nv_bfloat16 g_WL_hi[L_DIM * K_DIM],            g_WL_lo[L_DIM * K_DIM];
__device__ __nv_bfloat16 g_Wimg_hi[NHEADS * L_DIM * K_DIM], g_Wimg_lo[NHEADS * L_DIM * K_DIM];
__device__ __nv_bfloat16 g_Wf_hi[L_DIM * K_DIM],            g_Wf_lo[L_DIM * K_DIM];
__device__ __nv_bfloat16 g_PT_hi[N_DIM * K_DIM],            g_PT_lo[N_DIM * K_DIM];  // point^T
__device__ __nv_bfloat16 g_IT_hi[N_DIM * K_DIM],            g_IT_lo[N_DIM * K_DIM];  // img^T
__device__ __nv_bfloat16 g_FT_hi[N_DIM * K_DIM],            g_FT_lo[N_DIM * K_DIM];  // fused^T

// ---------------- PTX helpers (sm_80-portable only!) ----------------
__device__ __forceinline__ uint32_t smem_u32(const void* p) {
    uint32_t r;
    asm("{ .reg .u64 t; cvta.to.shared.u64 t, %1; cvt.u32.u64 %0, t; }" : "=r"(r) : "l"(p));
    return r;
}
__device__ __forceinline__ void cp16(uint32_t dst, const void* src) {
    asm volatile("cp.async.cg.shared.global [%0], [%1], 16;" :: "r"(dst), "l"(src) : "memory");
}
__device__ __forceinline__ void cp_commit() {
    asm volatile("cp.async.commit_group;" ::: "memory");
}
__device__ __forceinline__ void cp_wait1() {
    asm volatile("cp.async.wait_group 1;" ::: "memory");
}
__device__ __forceinline__ void ldsm_x4(uint32_t& r0, uint32_t& r1, uint32_t& r2, uint32_t& r3,
                                        uint32_t addr) {
    asm volatile("ldmatrix.sync.aligned.m8n8.x4.shared.b16 {%0,%1,%2,%3}, [%4];"
                 : "=r"(r0), "=r"(r1), "=r"(r2), "=r"(r3) : "r"(addr));
}
__device__ __forceinline__ void mma_bf16(float* c, const uint32_t* a, uint32_t b0, uint32_t b1) {
    asm volatile(
        "mma.sync.aligned.m16n8k16.row.col.f32.bf16.bf16.f32 "
        "{%0,%1,%2,%3}, {%4,%5,%6,%7}, {%8,%9}, {%0,%1,%2,%3};"
        : "+f"(c[0]), "+f"(c[1]), "+f"(c[2]), "+f"(c[3])
        : "r"(a[0]), "r"(a[1]), "r"(a[2]), "r"(a[3]), "r"(b0), "r"(b1));
}

// ---------------- bf16x3 mma.sync GEMM ----------------
// C[M, 4096] = (Ahi+Alo)[M,1024] * (Bhi+Blo)[4096,1024]^T + bias[m]
// BM=BN=128, BK=64, double-buffered cp.async, 8 warps (4x2), warp tile 32x64.
#define GBM 128
#define GBN 128
#define GBK 64
#define OFF_AH 0
#define OFF_AL 16384
#define OFF_BH 32768
#define OFF_BL 49152
#define STAGE_B 65536
#define GEMM_DSMEM (2 * STAGE_B)

__global__ __launch_bounds__(256, 1) void gemm_bf16x3(
    const __nv_bfloat16* __restrict__ Ahi, const __nv_bfloat16* __restrict__ Alo,
    const __nv_bfloat16* __restrict__ Bhi, const __nv_bfloat16* __restrict__ Blo,
    const float* __restrict__ bias, float* __restrict__ C, int M)
{
    extern __shared__ char sm_raw[];
    const uint32_t sbase = smem_u32(sm_raw);

    const int tid  = threadIdx.x;
    const int lane = tid & 31;
    const int wid  = tid >> 5;
    const int wm   = wid >> 1;          // 0..3, 32 rows each
    const int wn   = wid & 1;           // 0..1, 64 cols each
    const int bm   = blockIdx.y * GBM;
    const int bn   = blockIdx.x * GBN;

    // cp.async chunk coords (4 chunks per operand per thread)
    int crow[4], ccol[4];
    uint32_t cdst[4];
    #pragma unroll
    for (int t = 0; t < 4; t++) {
        int idx = (t << 8) + tid;       // 0..1023
        int r = idx >> 3, c = idx & 7;
        crow[t] = r; ccol[t] = c;
        cdst[t] = (uint32_t)((r << 7) + ((c ^ (r & 7)) << 4));
    }

    auto issue_stage = [&](int kstage, int buf) {
        const uint32_t sb = sbase + buf * STAGE_B;
        const int k0 = kstage * GBK;
        #pragma unroll
        for (int t = 0; t < 4; t++) {
            const int r = crow[t], c = ccol[t];
            const size_t ka = (size_t)(bm + r) * K_DIM + k0 + (c << 3);
            const size_t kb = (size_t)(bn + r) * K_DIM + k0 + (c << 3);
            cp16(sb + OFF_AH + cdst[t], Ahi + ka);
            cp16(sb + OFF_AL + cdst[t], Alo + ka);
            cp16(sb + OFF_BH + cdst[t], Bhi + kb);
            cp16(sb + OFF_BL + cdst[t], Blo + kb);
        }
    };

    // accumulators: 2 m-tiles x 8 n-tiles x 4 regs
    float acc[2][8][4];
    #pragma unroll
    for (int m = 0; m < 2; m++)
        #pragma unroll
        for (int n = 0; n < 8; n++)
            #pragma unroll
            for (int v = 0; v < 4; v++)
                acc[m][n][v] = 0.0f;

    // ldmatrix row/chunk bases
    const int a_row0 = wm * 32 + (lane & 15);       // + mt*16
    const int a_ch0  = lane >> 4;                   // + ks*2
    const int b_row0 = wn * 64 + ((lane >> 4) << 3) + (lane & 7);  // + np*16
    const int b_ch0  = (lane >> 3) & 1;             // + ks*2

    issue_stage(0, 0);
    cp_commit();

    const int KSTAGES = K_DIM / GBK;   // 16
    for (int i = 0; i < KSTAGES; i++) {
        const int p = i & 1;
        if (i + 1 < KSTAGES) issue_stage(i + 1, (i + 1) & 1);
        cp_commit();
        cp_wait1();
        __syncthreads();

        const uint32_t st = sbase + p * STAGE_B;
        #pragma unroll
        for (int ks = 0; ks < 4; ks++) {
            uint32_t ah[2][4], al[2][4], bh[4][4], bl[4][4];
            #pragma unroll
            for (int mt = 0; mt < 2; mt++) {
                const int r = a_row0 + mt * 16;
                const int ch = ks * 2 + a_ch0;
                const uint32_t ad = st + (r << 7) + (((ch ^ (r & 7))) << 4);
                ldsm_x4(ah[mt][0], ah[mt][1], ah[mt][2], ah[mt][3], ad + OFF_AH);
                ldsm_x4(al[mt][0], al[mt][1], al[mt][2], al[mt][3], ad + OFF_AL);
            }
            #pragma unroll
            for (int np = 0; np < 4; np++) {
                const int r = b_row0 + np * 16;
                const int ch = ks * 2 + b_ch0;
                const uint32_t bd = st + (r << 7) + (((ch ^ (r & 7))) << 4);
                ldsm_x4(bh[np][0], bh[np][1], bh[np][2], bh[np][3], bd + OFF_BH);
                ldsm_x4(bl[np][0], bl[np][1], bl[np][2], bl[np][3], bd + OFF_BL);
            }
            // pass 1: Ahi * Bhi
            #pragma unroll
            for (int mt = 0; mt < 2; mt++)
                #pragma unroll
                for (int np = 0; np < 4; np++) {
                    mma_bf16(acc[mt][np * 2 + 0], ah[mt], bh[np][0], bh[np][1]);
                    mma_bf16(acc[mt][np * 2 + 1], ah[mt], bh[np][2], bh[np][3]);
                }
            // pass 2: Ahi * Blo
            #pragma unroll
            for (int mt = 0; mt < 2; mt++)
                #pragma unroll
                for (int np = 0; np < 4; np++) {
                    mma_bf16(acc[mt][np * 2 + 0], ah[mt], bl[np][0], bl[np][1]);
                    mma_bf16(acc[mt][np * 2 + 1], ah[mt], bl[np][2], bl[np][3]);
                }
            // pass 3: Alo * Bhi
            #pragma unroll
            for (int mt = 0; mt < 2; mt++)
                #pragma unroll
                for (int np = 0; np < 4; np++) {
                    mma_bf16(acc[mt][np * 2 + 0], al[mt], bh[np][0], bh[np][1]);
                    mma_bf16(acc[mt][np * 2 + 1], al[mt], bh[np][2], bh[np][3]);
                }
        }
        __syncthreads();
    }

    // epilogue: direct stores + bias
    #pragma unroll
    for (int mt = 0; mt < 2; mt++) {
        const int row = bm + wm * 32 + mt * 16 + (lane >> 2);
        const float bv0 = bias[row], bv8 = bias[row + 8];
        #pragma unroll
        for (int nt = 0; nt < 8; nt++) {
            const int col = bn + wn * 64 + nt * 8 + (lane & 3) * 2;
            float2 v0 = make_float2(acc[mt][nt][0] + bv0, acc[mt][nt][1] + bv0);
            float2 v1 = make_float2(acc[mt][nt][2] + bv8, acc[mt][nt][3] + bv8);
            *reinterpret_cast<float2*>(&C[(size_t)row * N_DIM + col])       = v0;
            *reinterpret_cast<float2*>(&C[(size_t)(row + 8) * N_DIM + col]) = v1;
        }
    }
}

// ---------------- fp32 -> bf16 hi/lo split (weights) ----------------
__global__ __launch_bounds__(256) void split_w(
    const float* __restrict__ X, __nv_bfloat16* __restrict__ hi,
    __nv_bfloat16* __restrict__ lo, int n)
{
    int i = blockIdx.x * 256 + threadIdx.x;
    if (i < n) {
        float v = X[i];
        __nv_bfloat16 h = __float2bfloat16(v);
        hi[i] = h;
        lo[i] = __float2bfloat16(v - __bfloat162float(h));
    }
}

// ---------------- fp32 [K, N] -> bf16 hi/lo [N, K] split-transpose ----------------
__global__ __launch_bounds__(256) void split_transpose(
    const float* __restrict__ X, __nv_bfloat16* __restrict__ Thi,
    __nv_bfloat16* __restrict__ Tlo)
{
    __shared__ float t[32][33];
    int n0 = blockIdx.x * 32, k0 = blockIdx.y * 32;
    int tx = threadIdx.x & 31, ty = threadIdx.x >> 5;   // 32 x 8
    #pragma unroll
    for (int j = 0; j < 32; j += 8)
        t[ty + j][tx] = X[(size_t)(k0 + ty + j) * N_DIM + n0 + tx];
    __syncthreads();
    #pragma unroll
    for (int j = 0; j < 32; j += 8) {
        float v = t[tx][ty + j];
        __nv_bfloat16 h = __float2bfloat16(v);
        size_t o = (size_t)(n0 + ty + j) * K_DIM + k0 + tx;
        Thi[o] = h;
        Tlo[o] = __float2bfloat16(v - __bfloat162float(h));
    }
}

// ---------------- score partials ----------------
__global__ __launch_bounds__(256) void score_partial(
    const float* __restrict__ keys, const float* __restrict__ q,
    float* __restrict__ partial)
{
    int n = blockIdx.x * 256 + threadIdx.x;
    int chunk = blockIdx.y;
    int c0 = chunk * (L_DIM / NCHUNK);
    float s[NHEADS] = {0.f, 0.f, 0.f, 0.f};
    for (int c = c0; c < c0 + L_DIM / NCHUNK; c++) {
        float qv = q[(size_t)c * N_DIM + n];
        #pragma unroll
        for (int h = 0; h < NHEADS; h++)
            s[h] += keys[((size_t)(h * L_DIM + c)) * N_DIM + n] * qv;
    }
    #pragma unroll
    for (int h = 0; h < NHEADS; h++)
        partial[((size_t)chunk * NHEADS + h) * N_DIM + n] = s[h];
}

// ---------------- softmax over heads ----------------
__global__ __launch_bounds__(256) void softmax_heads(
    const float* __restrict__ partial, float* __restrict__ weight,
    float* __restrict__ wmap_out)
{
    int n = blockIdx.x * 256 + threadIdx.x;
    float s[NHEADS] = {0.f, 0.f, 0.f, 0.f};
    for (int ch = 0; ch < NCHUNK; ch++)
        #pragma unroll
        for (int h = 0; h < NHEADS; h++)
            s[h] += partial[((size_t)ch * NHEADS + h) * N_DIM + n];
    const float inv_sqrt_dk = 1.0f / 32.0f;
    float m = -1e30f;
    #pragma unroll
    for (int h = 0; h < NHEADS; h++) { s[h] *= inv_sqrt_dk; m = fmaxf(m, s[h]); }
    float e[NHEADS], sum = 0.f;
    #pragma unroll
    for (int h = 0; h < NHEADS; h++) { e[h] = __expf(s[h] - m); sum += e[h]; }
    float inv = 1.0f / sum;
    #pragma unroll
    for (int h = 0; h < NHEADS; h++) {
        float wv = e[h] * inv;
        weight[(size_t)h * N_DIM + n]   = wv;
        wmap_out[(size_t)h * N_DIM + n] = wv;
    }
}

// ---------------- z + residual + LayerNorm ----------------
__global__ __launch_bounds__(256) void z_layernorm(
    const float* __restrict__ keys, const float* __restrict__ q,
    const float* __restrict__ weight, const float* __restrict__ gamma,
    const float* __restrict__ beta, float* __restrict__ fused)
{
    int c = blockIdx.x;
    __shared__ float t[N_DIM];
    __shared__ float r1[8], r2[8];
    __shared__ float s_mean, s_rstd;

    float lsum = 0.f, lsq = 0.f;
    for (int n = threadIdx.x; n < N_DIM; n += 256) {
        float v = q[(size_t)c * N_DIM + n];
        #pragma unroll
        for (int h = 0; h < NHEADS; h++)
            v += weight[(size_t)h * N_DIM + n] *
                 keys[((size_t)(h * L_DIM + c)) * N_DIM + n];
        t[n] = v;
        lsum += v; lsq += v * v;
    }
    #pragma unroll
    for (int o = 16; o > 0; o >>= 1) {
        lsum += __shfl_xor_sync(0xffffffffu, lsum, o);
        lsq  += __shfl_xor_sync(0xffffffffu, lsq, o);
    }
    int wid = threadIdx.x >> 5, lid = threadIdx.x & 31;
    if (lid == 0) { r1[wid] = lsum; r2[wid] = lsq; }
    __syncthreads();
    if (threadIdx.x == 0) {
        float ts = 0.f, tq = 0.f;
        #pragma unroll
        for (int i = 0; i < 8; i++) { ts += r1[i]; tq += r2[i]; }
        float mean = ts * (1.0f / N_DIM);
        float var  = tq * (1.0f / N_DIM) - mean * mean;
        s_mean = mean;
        s_rstd = rsqrtf(var + 1e-5f);
    }
    __syncthreads();
    float mean = s_mean, rstd = s_rstd;
    for (int n = threadIdx.x; n < N_DIM; n += 256)
        fused[(size_t)c * N_DIM + n] = (t[n] - mean) * rstd * gamma[n] + beta[n];
}

// ---------------- launch ----------------
extern "C" void kernel_launch(void* const* d_in, const int* in_sizes, int n_in,
                              void* d_out, int out_size)
{
    const float* point = (const float*)d_in[0];
    const float* img   = (const float*)d_in[1];
    const float* W_img = (const float*)d_in[2];
    const float* b_img = (const float*)d_in[3];
    const float* W_L   = (const float*)d_in[4];
    const float* b_L   = (const float*)d_in[5];
    const float* ln_g  = (const float*)d_in[6];
    const float* ln_b  = (const float*)d_in[7];
    const float* W_f   = (const float*)d_in[8];
    const float* b_f   = (const float*)d_in[9];

    float* out  = (float*)d_out;
    float* wmap = out + (size_t)L_DIM * N_DIM;

    float *q, *keys, *partial, *weight, *fused;
    cudaGetSymbolAddress((void**)&q,       g_q);
    cudaGetSymbolAddress((void**)&keys,    g_keys);
    cudaGetSymbolAddress((void**)&partial, g_partial);
    cudaGetSymbolAddress((void**)&weight,  g_weight);
    cudaGetSymbolAddress((void**)&fused,   g_fused);

    __nv_bfloat16 *WLh, *WLl, *WIh, *WIl, *WFh, *WFl, *PTh, *PTl, *ITh, *ITl, *FTh, *FTl;
    cudaGetSymbolAddress((void**)&WLh, g_WL_hi);   cudaGetSymbolAddress((void**)&WLl, g_WL_lo);
    cudaGetSymbolAddress((void**)&WIh, g_Wimg_hi); cudaGetSymbolAddress((void**)&WIl, g_Wimg_lo);
    cudaGetSymbolAddress((void**)&WFh, g_Wf_hi);   cudaGetSymbolAddress((void**)&WFl, g_Wf_lo);
    cudaGetSymbolAddress((void**)&PTh, g_PT_hi);   cudaGetSymbolAddress((void**)&PTl, g_PT_lo);
    cudaGetSymbolAddress((void**)&ITh, g_IT_hi);   cudaGetSymbolAddress((void**)&ITl, g_IT_lo);
    cudaGetSymbolAddress((void**)&FTh, g_FT_hi);   cudaGetSymbolAddress((void**)&FTl, g_FT_lo);

    cudaFuncSetAttribute(gemm_bf16x3, cudaFuncAttributeMaxDynamicSharedMemorySize, GEMM_DSMEM);

    // split weights to bf16 hi/lo
    split_w<<<(L_DIM * K_DIM + 255) / 256, 256>>>(W_L, WLh, WLl, L_DIM * K_DIM);
    split_w<<<(NHEADS * L_DIM * K_DIM + 255) / 256, 256>>>(W_img, WIh, WIl, NHEADS * L_DIM * K_DIM);
    split_w<<<(L_DIM * K_DIM + 255) / 256, 256>>>(W_f, WFh, WFl, L_DIM * K_DIM);

    // split + transpose activations: [1024, 4096] -> [4096, 1024] bf16 hi/lo
    split_transpose<<<dim3(N_DIM / 32, K_DIM / 32), 256>>>(point, PTh, PTl);
    split_transpose<<<dim3(N_DIM / 32, K_DIM / 32), 256>>>(img, ITh, ITl);

    // q = W_L * point + b_L
    gemm_bf16x3<<<dim3(N_DIM / GBN, L_DIM / GBM), 256, GEMM_DSMEM>>>(
        WLh, WLl, PTh, PTl, b_L, q, L_DIM);
    // keys = W_img * img + b_img (4 heads fused, M=4096)
    gemm_bf16x3<<<dim3(N_DIM / GBN, (NHEADS * L_DIM) / GBM), 256, GEMM_DSMEM>>>(
        WIh, WIl, ITh, ITl, b_img, keys, NHEADS * L_DIM);

    // attention
    score_partial<<<dim3(N_DIM / 256, NCHUNK), 256>>>(keys, q, partial);
    softmax_heads<<<N_DIM / 256, 256>>>(partial, weight, wmap);
    z_layernorm<<<L_DIM, 256>>>(keys, q, weight, ln_g, ln_b, fused);

    // fused -> bf16 hi/lo transposed
    split_transpose<<<dim3(N_DIM / 32, K_DIM / 32), 256>>>(fused, FTh, FTl);

    // out = W_f * fused + b_f
    gemm_bf16x3<<<dim3(N_DIM / GBN, L_DIM / GBM), 256, GEMM_DSMEM>>>(
        WFh, WFl, FTh, FTl, b_f, out, L_DIM);
}